// round 5
// baseline (speedup 1.0000x reference)
#include <cuda_runtime.h>
#include <cuda_fp16.h>
#include <cstdint>
#include <cstddef>

// out = x @ Wv^T + bv.  (Reference's softmax rows sum to 1 => its final
// einsum('btu,btj->btj', weights, v) == v + rounding; Q/K/softmax are dead.)
//
// fp32 GEMM M=8192, K=1024, N=64 on portable mma.sync m16n8k16 fp16:
//   xh = f16(x), xl = f16(x - xh), w = f16(W);  D = xh*w + xl*w (fp32 acc).
//   Error ~ x*(W - f16(W)) ~ 2.8e-4 relative (norm) << 1e-3.
// R5 structure: W pre-converted ONCE (wconv kernel) into MMA-fragment layout;
// main kernel cp.asyncs W frags to smem (double-buffered 16KB chunks, 8 syncs
// total), x streams gmem->registers directly in A-fragment shape (no A smem,
// no phase barriers) with 2-step prefetch distance.

#define NEMB    1024
#define NH      64
#define MT      64
#define THREADS 256
#define GRID    128              // 8192 / 64
#define NSTEP   64               // k16 steps over K=1024
#define CH      8                // chunks of 8 k-steps
#define SQ      8                // steps per chunk
#define CHB     16384            // bytes of wfrag per chunk (8*8*32*8)

// W fragments: [s 0..63][j 0..7][lane 0..31] -> uint2 {f16x2(k,k+1), f16x2(k+8,k+9)}
// with n = j*8 + (lane>>2), k = s*16 + (lane&3)*2
__device__ uint2 g_wfrag[64 * 8 * 32];

__global__ void wconv(const float* __restrict__ W)
{
    int id = blockIdx.x * blockDim.x + threadIdx.x;   // 0..16383
    int l = id & 31, j = (id >> 5) & 7, s = id >> 8;
    int n = j * 8 + (l >> 2);
    int k = s * 16 + (l & 3) * 2;
    const float* p = W + (size_t)n * NEMB + k;
    float2 w0 = *(const float2*)p;
    float2 w1 = *(const float2*)(p + 8);
    __half2 h0 = __float22half2_rn(w0);
    __half2 h1 = __float22half2_rn(w1);
    uint2 o;
    o.x = *(uint32_t*)&h0;
    o.y = *(uint32_t*)&h1;
    g_wfrag[id] = o;
}

__shared__ __align__(16) uint2 wsm[2][SQ][8][32];   // 32 KB
__shared__ float bias_s[NH];

__device__ __forceinline__ void mma16816(float* c,
                                         uint32_t a0, uint32_t a1, uint32_t a2, uint32_t a3,
                                         uint32_t b0, uint32_t b1)
{
    asm volatile(
        "mma.sync.aligned.m16n8k16.row.col.f32.f16.f16.f32 "
        "{%0,%1,%2,%3}, {%4,%5,%6,%7}, {%8,%9}, {%0,%1,%2,%3};"
        : "+f"(c[0]), "+f"(c[1]), "+f"(c[2]), "+f"(c[3])
        : "r"(a0), "r"(a1), "r"(a2), "r"(a3), "r"(b0), "r"(b1));
}

__device__ __forceinline__ void cp16(uint32_t s, const void* g)
{
    asm volatile("cp.async.cg.shared.global [%0], [%1], 16;" :: "r"(s), "l"(g));
}

__global__ void __launch_bounds__(THREADS)
vproj(const float* __restrict__ x, const float* __restrict__ bv,
      float* __restrict__ out)
{
    const int t   = threadIdx.x;
    const int wid = t >> 5;
    const int lid = t & 31;
    const int wm  = wid & 3;         // M slice of 16 rows
    const int wn  = wid >> 2;        // N half (4 n-tiles)
    const int rowbase = blockIdx.x * MT;

    if (t < 16) ((float4*)bias_s)[t] = ((const float4*)bv)[t];

    const uint32_t wsm_s = (uint32_t)__cvta_generic_to_shared(&wsm[0][0][0][0]);
    const char* wg = (const char*)g_wfrag;

    // chunk copy: 4 x 16B per thread
    auto copy_chunk = [&](int cc) {
#pragma unroll
        for (int i = 0; i < 4; i++) {
            uint32_t off = (uint32_t)(t + THREADS * i) * 16;
            cp16(wsm_s + (uint32_t)(cc & 1) * CHB + off,
                 wg + (size_t)cc * CHB + off);
        }
        asm volatile("cp.async.commit_group;");
    };

    // x fragment base: row = rowbase + wm*16 + (lid>>2), k offset (lid&3)*2
    const int arow = rowbase + wm * 16 + (lid >> 2);
    const float* xp = x + (size_t)arow * NEMB + (lid & 3) * 2;

    float acc[4][4];
#pragma unroll
    for (int j = 0; j < 4; j++)
#pragma unroll
        for (int e = 0; e < 4; e++) acc[j][e] = 0.0f;

    copy_chunk(0);
    copy_chunk(1);

    // x prefetch regs: 2 steps in flight. Order: a0(row,k) a1(row+8,k) a2(row,k+8) a3(row+8,k+8)
    float2 xq[2][4];
    auto load_x = [&](float2* d, int gs) {
        const float* p = xp + gs * 16;
        d[0] = *(const float2*)(p);
        d[1] = *(const float2*)(p + 8 * NEMB);
        d[2] = *(const float2*)(p + 8);
        d[3] = *(const float2*)(p + 8 * NEMB + 8);
    };
    load_x(xq[0], 0);
    load_x(xq[1], 1);

#pragma unroll 1
    for (int c = 0; c < CH; c++) {
        if (c == CH - 1) asm volatile("cp.async.wait_group 0;");
        else             asm volatile("cp.async.wait_group 1;");
        __syncthreads();

#pragma unroll
        for (int s = 0; s < SQ; s++) {
            const int gs = c * SQ + s;
            const int b  = gs & 1;

            // split held x into fp16 hi/lo fragments
            uint32_t ah[4], al[4];
#pragma unroll
            for (int i = 0; i < 4; i++) {
                float2 f = xq[b][i];
                __half2 h = __float22half2_rn(f);
                ah[i] = *(uint32_t*)&h;
                float2 hf = __half22float2(h);
                __half2 l2 = __float22half2_rn(make_float2(f.x - hf.x, f.y - hf.y));
                al[i] = *(uint32_t*)&l2;
            }
            // prefetch step gs+2 into the slot just consumed
            int nx = gs + 2; if (nx > NSTEP - 1) nx = NSTEP - 1;
            load_x(xq[b], nx);

#pragma unroll
            for (int j = 0; j < 4; j++) {
                uint2 wb = wsm[c & 1][s][wn * 4 + j][lid];
                mma16816(acc[j], ah[0], ah[1], ah[2], ah[3], wb.x, wb.y);
                mma16816(acc[j], al[0], al[1], al[2], al[3], wb.x, wb.y);
            }
        }
        __syncthreads();
        if (c + 2 < CH) copy_chunk(c + 2);
    }

    // epilogue: add bias, store float2 pairs
    const int orow = rowbase + wm * 16 + (lid >> 2);
#pragma unroll
    for (int j = 0; j < 4; j++) {
        const int col = (wn * 4 + j) * 8 + ((lid & 3) << 1);
        const float b0 = bias_s[col], b1 = bias_s[col + 1];
        float2 lo = make_float2(acc[j][0] + b0, acc[j][1] + b1);
        float2 hi = make_float2(acc[j][2] + b0, acc[j][3] + b1);
        *(float2*)(out + (size_t)orow * NH + col)       = lo;
        *(float2*)(out + (size_t)(orow + 8) * NH + col) = hi;
    }
}

extern "C" void kernel_launch(void* const* d_in, const int* in_sizes, int n_in,
                              void* d_out, int out_size)
{
    const float* x  = (const float*)d_in[0];
    const float* Wv = (const float*)d_in[5];
    const float* bv = (const float*)d_in[6];

    wconv<<<64, 256>>>(Wv);
    vproj<<<GRID, THREADS>>>(x, bv, (float*)d_out);
}